// round 12
// baseline (speedup 1.0000x reference)
#include <cuda_runtime.h>
#include <cstdint>

// Problem constants
#define BB   16
#define CC   256
#define HH   64
#define WW   64
#define KK   4
#define OO   256
#define HID  65
#define TEMP 34.0f

// Conv tiling: CTA 128(o) x 256(px), 512 thr = 16 warps of 64x32.
// K chunk = 32 ch (one cg); A 4-stage ring, B 2-stage, ONE barrier per chunk.
#define AST   40                       // A smem row stride (floats)
#define SA_SZ (128 * AST * 4)          // 20480 B per A stage
#define BROW  72                       // B smem row stride (floats)
#define BCH   440                      // B smem channel stride (floats) 6*72+8
#define SB_SZ (32 * BCH * 4)           // 56320 B per B stage
#define SB_OFF (4 * SA_SZ)             // 81920
#define SMEM_TOTAL (SB_OFF + 2 * SB_SZ)   // 194560 (190 KB)

// Scratch
__device__ float g_pooled[BB * CC];
__device__ float g_att[BB * KK];
__device__ float g_aggb[BB * OO];
__device__ float g_w[(size_t)BB * 9 * OO * CC];      // [b][tap][o][c'], k-permuted, tf32
__device__ float g_xr[(size_t)BB * CC * HH * WW];    // tf32-rounded x

__device__ __forceinline__ uint32_t smem_u32(const void* p) {
    uint32_t a;
    asm("{ .reg .u64 t; cvta.to.shared.u64 t, %1; cvt.u32.u64 %0, t; }" : "=r"(a) : "l"(p));
    return a;
}
__device__ __forceinline__ float to_tf32f(float f) {
    uint32_t r;
    asm("cvt.rna.tf32.f32 %0, %1;" : "=r"(r) : "f"(f));
    return __uint_as_float(r);
}
#define CP16(dst, src) \
    asm volatile("cp.async.cg.shared.global [%0], [%1], 16;" :: "r"(dst), "l"(src) : "memory")
#define CP16Z(dst, src, sz) \
    asm volatile("cp.async.cg.shared.global [%0], [%1], 16, %2;" :: "r"(dst), "l"(src), "r"(sz) : "memory")
#define CP_COMMIT() asm volatile("cp.async.commit_group;" ::: "memory")
#define CP_WAIT2()  asm volatile("cp.async.wait_group 2;" ::: "memory")

// ---------------------------------------------------------------------------
// K1: global average pool + tf32-rounded copy of x
// ---------------------------------------------------------------------------
__global__ void pool_kernel(const float* __restrict__ x) {
    int bc = blockIdx.x;
    const float4* xv = reinterpret_cast<const float4*>(x) + (size_t)bc * (HH * WW / 4);
    float4* xo = reinterpret_cast<float4*>(g_xr) + (size_t)bc * (HH * WW / 4);
    float s = 0.f;
    for (int i = threadIdx.x; i < HH * WW / 4; i += blockDim.x) {
        float4 v = xv[i];
        s += (v.x + v.y) + (v.z + v.w);
        float4 r;
        r.x = to_tf32f(v.x); r.y = to_tf32f(v.y);
        r.z = to_tf32f(v.z); r.w = to_tf32f(v.w);
        xo[i] = r;
    }
    #pragma unroll
    for (int off = 16; off > 0; off >>= 1)
        s += __shfl_down_sync(0xffffffffu, s, off);
    __shared__ float ws[8];
    int lane = threadIdx.x & 31, wid = threadIdx.x >> 5;
    if (lane == 0) ws[wid] = s;
    __syncthreads();
    if (threadIdx.x == 0) {
        float t = 0.f;
        int nw = blockDim.x >> 5;
        for (int i = 0; i < nw; i++) t += ws[i];
        g_pooled[bc] = t * (1.0f / (HH * WW));
    }
}

// ---------------------------------------------------------------------------
// K2: attention MLP + softmax + aggregated bias
// ---------------------------------------------------------------------------
__global__ void att_kernel(const float* __restrict__ w_fc1,
                           const float* __restrict__ w_fc2,
                           const float* __restrict__ b_fc2,
                           const float* __restrict__ bias) {
    int b = blockIdx.x;
    __shared__ float sp[CC];
    __shared__ float sh[HID];
    __shared__ float satt[KK];
    for (int i = threadIdx.x; i < CC; i += blockDim.x) sp[i] = g_pooled[b * CC + i];
    __syncthreads();
    if (threadIdx.x < HID) {
        float a = 0.f;
        const float* wr = w_fc1 + threadIdx.x * CC;
        for (int j = 0; j < CC; j++) a += sp[j] * wr[j];
        sh[threadIdx.x] = fmaxf(a, 0.f);
    }
    __syncthreads();
    if (threadIdx.x == 0) {
        float lg[KK];
        float m = -1e30f;
        for (int k = 0; k < KK; k++) {
            float a = b_fc2[k];
            for (int j = 0; j < HID; j++) a += sh[j] * w_fc2[k * HID + j];
            a *= (1.0f / TEMP);
            lg[k] = a;
            m = fmaxf(m, a);
        }
        float den = 0.f;
        for (int k = 0; k < KK; k++) { lg[k] = expf(lg[k] - m); den += lg[k]; }
        float inv = 1.0f / den;
        for (int k = 0; k < KK; k++) satt[k] = lg[k] * inv;
    }
    __syncthreads();
    if (threadIdx.x < KK) g_att[b * KK + threadIdx.x] = satt[threadIdx.x];
    for (int o = threadIdx.x; o < OO; o += blockDim.x) {
        float a = 0.f;
        #pragma unroll
        for (int k = 0; k < KK; k++) a += satt[k] * bias[k * OO + o];
        g_aggb[b * OO + o] = a;
    }
}

// ---------------------------------------------------------------------------
// K3: aggregate weights -> g_w[b][tap][o][c'] (k-permuted within 32-blocks,
// tf32-rounded). weight read ONCE total. One block per o; thread = c.
// Permutation: original k = 8ks + 4h + kq stored at pos = ks*8 + kq*2 + h,
// so the MMA A-fragment (k, k+4) pair is adjacent (LDS.64).
// ---------------------------------------------------------------------------
__global__ void aggw_kernel(const float* __restrict__ weight) {
    int o = blockIdx.x;
    int c = threadIdx.x;
    __shared__ float satt[BB * KK];
    if (c < BB * KK) satt[c] = g_att[c];
    __syncthreads();
    float wv[KK][9];
    #pragma unroll
    for (int k = 0; k < KK; k++) {
        const float* wp = weight + (((size_t)k * OO + o) * CC + c) * 9;
        #pragma unroll
        for (int t = 0; t < 9; t++) wv[k][t] = wp[t];
    }
    int j = c & 31;
    int cstore = (c & ~31) | ((j >> 3) * 8 + (j & 3) * 2 + ((j >> 2) & 1));
    for (int b = 0; b < BB; b++) {
        float a0 = satt[b * KK + 0], a1 = satt[b * KK + 1];
        float a2 = satt[b * KK + 2], a3 = satt[b * KK + 3];
        #pragma unroll
        for (int t = 0; t < 9; t++) {
            float v = a0 * wv[0][t] + a1 * wv[1][t] + a2 * wv[2][t] + a3 * wv[3][t];
            g_w[(((size_t)b * 9 + t) * OO + o) * CC + cstore] = to_tf32f(v);
        }
    }
}

// ---------------------------------------------------------------------------
// K4: TF32 mma.sync implicit-GEMM conv.
// 512 thr = 16 warps (2 o-halves x 8 px-groups of 32).  Warp tile 64x32
// (4x4 m16n8k8, acc=64 regs -> <=128 regs/thread, full-RF CTA).
// A: 4-stage ring; B raw-x (32ch x 6 rows): 2 stages by cg parity, slices
// staged during taps 1..6 of the previous cg.  ONE __syncthreads per chunk.
// ---------------------------------------------------------------------------
__global__ void __launch_bounds__(512, 1)
conv_mma_kernel(float* __restrict__ out) {
    extern __shared__ char smem[];
    float* smf = (float*)smem;
    const uint32_t sbu = smem_u32(smem);
    const int tid  = threadIdx.x;
    const int lane = tid & 31;
    const int w    = tid >> 5;
    const int wo   = w >> 3;              // 0..1  (o half)
    const int wp   = w & 7;               // 0..7  (32-px group)
    const int pr   = wp >> 1;             // image row within tile (0..3)
    const int ph   = wp & 1;              // column half (0..1)
    const int gid  = lane >> 2;           // 0..7
    const int kq   = lane & 3;            // 0..3
    const int b  = blockIdx.x;
    const int o0 = blockIdx.y * 128;
    const int r0 = blockIdx.z * 4;        // 4 image rows per CTA

    const float* xb = g_xr + (size_t)b * CC * HH * WW;
    const float* wb = g_w  + (size_t)b * 9 * OO * CC;

    // zero always-zero halo columns (3 : x col -1, 68 : x col 64), both B stages
    for (int i = tid; i < 2 * 32 * 6 * 2; i += 512) {
        int st  = i / 384;
        int rem = i - st * 384;
        int c = rem / 12, r2 = rem - c * 12;
        int rr = r2 >> 1, h = r2 & 1;
        smf[(SB_OFF / 4) + st * (SB_SZ / 4) + c * BCH + rr * BROW + (h ? 68 : 3)] = 0.f;
    }

    float acc[4][4][4];
    #pragma unroll
    for (int mi = 0; mi < 4; mi++)
        #pragma unroll
        for (int ni = 0; ni < 4; ni++)
            #pragma unroll
            for (int q = 0; q < 4; q++) acc[mi][ni][q] = 0.f;

    // ---- staging helpers (512 threads)
    auto stageA = [&](int ch) {                      // 2x 16B per thread
        int cg = ch / 9, tap = ch - cg * 9;
        uint32_t dst0 = sbu + (uint32_t)((ch & 3) * SA_SZ);
        const float* src0 = wb + ((size_t)tap * OO + o0) * CC + cg * 32;
        #pragma unroll
        for (int i = 0; i < 2; i++) {
            int e = tid + i * 512;
            int row = e >> 3, c4 = (e & 7) * 4;
            CP16(dst0 + (uint32_t)((row * AST + c4) * 4), src0 + (size_t)row * CC + c4);
        }
    };
    auto stageBslice = [&](int cg, int k) {          // one 16B op; k in 0..5
        int j = tid + k * 512;                       // j in [0, 3072)
        int c = j / 96, rem = j - c * 96;
        int row = rem >> 4, seg = rem & 15;
        int rr = r0 - 1 + row;
        bool ok = (unsigned)rr < (unsigned)HH;
        const float* src = xb + ((size_t)(cg * 32 + c) * HH + (ok ? rr : 0)) * WW + seg * 4;
        uint32_t dst = sbu + SB_OFF + (uint32_t)((cg & 1) * SB_SZ)
                     + (uint32_t)((c * BCH + row * BROW + 4 + seg * 4) * 4);
        CP16Z(dst, src, ok ? 16 : 0);
    };

    // boot: group -2 = full B(0) + A(0);  group -1 = A(1)
    #pragma unroll
    for (int k = 0; k < 6; k++) stageBslice(0, k);
    stageA(0);
    CP_COMMIT();
    stageA(1);
    CP_COMMIT();

    for (int ch = 0; ch < 72; ch++) {
        const int cg = ch / 9, tap = ch - cg * 9;

        // stage ahead (A two chunks out; B for next cg during taps 1..6)
        if (ch + 2 < 72) stageA(ch + 2);
        if (tap >= 1 && tap <= 6 && cg + 1 < 8) stageBslice(cg + 1, tap - 1);
        CP_COMMIT();
        CP_WAIT2();                                   // A(ch) + B(cg) resident
        __syncthreads();                              // visibility + overwrite fence

        const int dy = tap / 3 - 1, dx = tap - (tap / 3) * 3 - 1;
        const float* A  = smf + (ch & 3) * (SA_SZ / 4) + (wo * 64 + gid) * AST;
        const float* Bc = smf + (SB_OFF / 4) + (cg & 1) * (SB_SZ / 4)
                        + (1 + pr + dy) * BROW + 4 + ph * 32 + gid + dx;

        #pragma unroll
        for (int ks = 0; ks < 4; ks++) {
            uint2 alo[4], ahi[4];
            #pragma unroll
            for (int mi = 0; mi < 4; mi++) {
                const float* p = A + mi * 16 * AST + ks * 8 + kq * 2;
                alo[mi] = *(const uint2*)p;
                ahi[mi] = *(const uint2*)(p + 8 * AST);
            }
            uint32_t bfr[4][2];
            const float* Bk = Bc + (ks * 8 + kq) * BCH;
            #pragma unroll
            for (int ni = 0; ni < 4; ni++) {
                bfr[ni][0] = __float_as_uint(Bk[ni * 8]);
                bfr[ni][1] = __float_as_uint(Bk[4 * BCH + ni * 8]);
            }
            #pragma unroll
            for (int mi = 0; mi < 4; mi++)
                #pragma unroll
                for (int ni = 0; ni < 4; ni++) {
                    asm volatile(
                        "mma.sync.aligned.m16n8k8.row.col.f32.tf32.tf32.f32 "
                        "{%0,%1,%2,%3}, {%4,%5,%6,%7}, {%8,%9}, {%0,%1,%2,%3};"
                        : "+f"(acc[mi][ni][0]), "+f"(acc[mi][ni][1]),
                          "+f"(acc[mi][ni][2]), "+f"(acc[mi][ni][3])
                        : "r"(alo[mi].x), "r"(ahi[mi].x), "r"(alo[mi].y), "r"(ahi[mi].y),
                          "r"(bfr[ni][0]), "r"(bfr[ni][1]));
                }
        }
    }

    // epilogue: bias + float2 stores.  px row = r0+pr, col = ph*32 + ni*8 + kq*2
    const float* abp = g_aggb + b * OO;
    #pragma unroll
    for (int mi = 0; mi < 4; mi++) {
        const int o1 = o0 + wo * 64 + mi * 16 + gid;
        const float bv1 = abp[o1], bv2 = abp[o1 + 8];
        float* p1 = out + (((size_t)b * OO + o1) * HH + r0 + pr) * WW + ph * 32 + 2 * kq;
        float* p2 = p1 + (size_t)8 * HH * WW;
        #pragma unroll
        for (int ni = 0; ni < 4; ni++) {
            *(float2*)(p1 + ni * 8) = make_float2(acc[mi][ni][0] + bv1, acc[mi][ni][1] + bv1);
            *(float2*)(p2 + ni * 8) = make_float2(acc[mi][ni][2] + bv2, acc[mi][ni][3] + bv2);
        }
    }
}

// ---------------------------------------------------------------------------
extern "C" void kernel_launch(void* const* d_in, const int* in_sizes, int n_in,
                              void* d_out, int out_size) {
    const float* x      = (const float*)d_in[0];
    const float* w_fc1  = (const float*)d_in[1];
    const float* w_fc2  = (const float*)d_in[2];
    const float* b_fc2  = (const float*)d_in[3];
    const float* weight = (const float*)d_in[4];
    const float* bias   = (const float*)d_in[5];
    float* out = (float*)d_out;

    cudaFuncSetAttribute(conv_mma_kernel,
                         cudaFuncAttributeMaxDynamicSharedMemorySize, SMEM_TOTAL);

    pool_kernel<<<BB * CC, 256>>>(x);
    att_kernel<<<BB, 128>>>(w_fc1, w_fc2, b_fc2, bias);
    aggw_kernel<<<OO, 256>>>(weight);
    conv_mma_kernel<<<dim3(BB, OO / 128, HH / 4), 512, SMEM_TOTAL>>>(out);
}

// round 14
// speedup vs baseline: 1.6168x; 1.6168x over previous
#include <cuda_runtime.h>
#include <cuda_fp16.h>
#include <cstdint>

// Problem constants
#define BB   16
#define CC   256
#define HH   64
#define WW   64
#define KK   4
#define OO   256
#define HID  65
#define TEMP 34.0f
#define C2   128                        // channel pairs

// Conv tiling: CTA 128(o) x 256(px), 512 thr = 16 warps of 64x32.
// K chunk = 32 ch = 2 x k16 MMA steps.  fp16 data, fp32 accumulate.
#define AST2  24                        // A smem row stride (half2 units, 96 B)
#define SA_SZ (128 * AST2 * 4)          // 12288 B per A stage
#define BROW2 72                        // B row stride (half2)
#define BCH2  440                       // B c2-row stride (half2) = 6*72+8
#define SB_SZ (16 * BCH2 * 4)           // 28160 B per B stage (16 c2-rows)
#define SB_OFF (4 * SA_SZ)              // 49152
#define SMEM_TOTAL (SB_OFF + 2 * SB_SZ) // 105472 (103 KB)

// Scratch
__device__ float  g_pooled[BB * CC];
__device__ float  g_att[BB * KK];
__device__ float  g_aggb[BB * OO];
__device__ __half2 g_wh[(size_t)BB * 9 * OO * C2];       // [b][tap][o][c2'], perm, fp16
__device__ __half2 g_xh[(size_t)BB * C2 * HH * WW];      // [b][c2][p], (even,odd) ch

__device__ __forceinline__ uint32_t smem_u32(const void* p) {
    uint32_t a;
    asm("{ .reg .u64 t; cvta.to.shared.u64 t, %1; cvt.u32.u64 %0, t; }" : "=r"(a) : "l"(p));
    return a;
}
#define CP16(dst, src) \
    asm volatile("cp.async.cg.shared.global [%0], [%1], 16;" :: "r"(dst), "l"(src) : "memory")
#define CP16Z(dst, src, sz) \
    asm volatile("cp.async.cg.shared.global [%0], [%1], 16, %2;" :: "r"(dst), "l"(src), "r"(sz) : "memory")
#define CP_COMMIT() asm volatile("cp.async.commit_group;" ::: "memory")
#define CP_WAIT2()  asm volatile("cp.async.wait_group 2;" ::: "memory")

// ---------------------------------------------------------------------------
// K1: global average pool (fp32) + fp16 channel-pair-interleaved copy of x.
// One block per (b, c2): handles channels 2c2, 2c2+1.
// ---------------------------------------------------------------------------
__global__ void pool_kernel(const float* __restrict__ x) {
    int blk = blockIdx.x;
    int b = blk >> 7, c2 = blk & 127;
    const float4* p0 = reinterpret_cast<const float4*>(x + ((size_t)(b * CC + 2 * c2)) * (HH * WW));
    const float4* p1 = reinterpret_cast<const float4*>(x + ((size_t)(b * CC + 2 * c2 + 1)) * (HH * WW));
    uint4* xo = reinterpret_cast<uint4*>(g_xh + ((size_t)(b * C2 + c2)) * (HH * WW));
    float sa = 0.f, sb = 0.f;
    for (int i = threadIdx.x; i < HH * WW / 4; i += blockDim.x) {
        float4 va = p0[i], vb = p1[i];
        sa += (va.x + va.y) + (va.z + va.w);
        sb += (vb.x + vb.y) + (vb.z + vb.w);
        __half2 h0 = __halves2half2(__float2half_rn(va.x), __float2half_rn(vb.x));
        __half2 h1 = __halves2half2(__float2half_rn(va.y), __float2half_rn(vb.y));
        __half2 h2 = __halves2half2(__float2half_rn(va.z), __float2half_rn(vb.z));
        __half2 h3 = __halves2half2(__float2half_rn(va.w), __float2half_rn(vb.w));
        uint4 o;
        o.x = *(uint32_t*)&h0; o.y = *(uint32_t*)&h1;
        o.z = *(uint32_t*)&h2; o.w = *(uint32_t*)&h3;
        xo[i] = o;
    }
    #pragma unroll
    for (int off = 16; off > 0; off >>= 1) {
        sa += __shfl_down_sync(0xffffffffu, sa, off);
        sb += __shfl_down_sync(0xffffffffu, sb, off);
    }
    __shared__ float wsa[8], wsb[8];
    int lane = threadIdx.x & 31, wid = threadIdx.x >> 5;
    if (lane == 0) { wsa[wid] = sa; wsb[wid] = sb; }
    __syncthreads();
    if (threadIdx.x == 0) {
        float ta = 0.f, tb = 0.f;
        int nw = blockDim.x >> 5;
        for (int i = 0; i < nw; i++) { ta += wsa[i]; tb += wsb[i]; }
        g_pooled[b * CC + 2 * c2]     = ta * (1.0f / (HH * WW));
        g_pooled[b * CC + 2 * c2 + 1] = tb * (1.0f / (HH * WW));
    }
}

// ---------------------------------------------------------------------------
// K2: attention MLP + softmax + aggregated bias
// ---------------------------------------------------------------------------
__global__ void att_kernel(const float* __restrict__ w_fc1,
                           const float* __restrict__ w_fc2,
                           const float* __restrict__ b_fc2,
                           const float* __restrict__ bias) {
    int b = blockIdx.x;
    __shared__ float sp[CC];
    __shared__ float sh[HID];
    __shared__ float satt[KK];
    for (int i = threadIdx.x; i < CC; i += blockDim.x) sp[i] = g_pooled[b * CC + i];
    __syncthreads();
    if (threadIdx.x < HID) {
        float a = 0.f;
        const float* wr = w_fc1 + threadIdx.x * CC;
        for (int j = 0; j < CC; j++) a += sp[j] * wr[j];
        sh[threadIdx.x] = fmaxf(a, 0.f);
    }
    __syncthreads();
    if (threadIdx.x == 0) {
        float lg[KK];
        float m = -1e30f;
        for (int k = 0; k < KK; k++) {
            float a = b_fc2[k];
            for (int j = 0; j < HID; j++) a += sh[j] * w_fc2[k * HID + j];
            a *= (1.0f / TEMP);
            lg[k] = a;
            m = fmaxf(m, a);
        }
        float den = 0.f;
        for (int k = 0; k < KK; k++) { lg[k] = expf(lg[k] - m); den += lg[k]; }
        float inv = 1.0f / den;
        for (int k = 0; k < KK; k++) satt[k] = lg[k] * inv;
    }
    __syncthreads();
    if (threadIdx.x < KK) g_att[b * KK + threadIdx.x] = satt[threadIdx.x];
    for (int o = threadIdx.x; o < OO; o += blockDim.x) {
        float a = 0.f;
        #pragma unroll
        for (int k = 0; k < KK; k++) a += satt[k] * bias[k * OO + o];
        g_aggb[b * OO + o] = a;
    }
}

// ---------------------------------------------------------------------------
// K3: aggregate weights -> g_wh[b][tap][o][c2'] (fp16 half2, perm within
// 8-half2 k16-blocks: j<4 -> 2j, j>=4 -> 2(j-4)+1 so lane kq's (a0,a2) pair
// is one LDS.64).  weight read ONCE.  One block per o; thread = c2.
// ---------------------------------------------------------------------------
__global__ void aggw_kernel(const float* __restrict__ weight) {
    int o = blockIdx.x;
    int c2 = threadIdx.x;              // 0..127
    __shared__ float satt[BB * KK];
    if (c2 < BB * KK) satt[c2] = g_att[c2];
    __syncthreads();
    float wv0[KK][9], wv1[KK][9];
    #pragma unroll
    for (int k = 0; k < KK; k++) {
        const float* wp = weight + (((size_t)k * OO + o) * CC + 2 * c2) * 9;
        #pragma unroll
        for (int t = 0; t < 9; t++) { wv0[k][t] = wp[t]; wv1[k][t] = wp[9 + t]; }
    }
    int j = c2 & 7;
    int cpos = (c2 & ~7) | ((j < 4) ? (2 * j) : (2 * (j - 4) + 1));
    for (int b = 0; b < BB; b++) {
        float a0 = satt[b * KK + 0], a1 = satt[b * KK + 1];
        float a2 = satt[b * KK + 2], a3 = satt[b * KK + 3];
        #pragma unroll
        for (int t = 0; t < 9; t++) {
            float v0 = a0 * wv0[0][t] + a1 * wv0[1][t] + a2 * wv0[2][t] + a3 * wv0[3][t];
            float v1 = a0 * wv1[0][t] + a1 * wv1[1][t] + a2 * wv1[2][t] + a3 * wv1[3][t];
            g_wh[(((size_t)b * 9 + t) * OO + o) * C2 + cpos] =
                __halves2half2(__float2half_rn(v0), __float2half_rn(v1));
        }
    }
}

// ---------------------------------------------------------------------------
// K4: fp16 m16n8k16 mma.sync implicit-GEMM conv.
// 512 thr = 16 warps (2 o-halves x 8 px-groups of 32).  Warp tile 64x32.
// Chunk = 32 channels = 2 k16 steps.  A 4-stage ring, B (16 c2 x 6 raw rows)
// 2-stage by cg parity, reused across 9 taps.  One __syncthreads per chunk.
// ---------------------------------------------------------------------------
__global__ void __launch_bounds__(512, 1)
conv_mma_kernel(float* __restrict__ out) {
    extern __shared__ char smem[];
    __half2* smh = (__half2*)smem;
    const uint32_t sbu = smem_u32(smem);
    const int tid  = threadIdx.x;
    const int lane = tid & 31;
    const int w    = tid >> 5;
    const int wo   = w >> 3;              // 0..1  (o half)
    const int wp   = w & 7;               // 0..7  (32-px group)
    const int pr   = wp >> 1;             // image row in tile (0..3)
    const int ph   = wp & 1;              // column half
    const int gid  = lane >> 2;           // 0..7
    const int kq   = lane & 3;            // 0..3
    const int b  = blockIdx.x;
    const int o0 = blockIdx.y * 128;
    const int r0 = blockIdx.z * 4;

    const __half2* xb = g_xh + (size_t)b * C2 * HH * WW;
    const __half2* wb = g_wh + (size_t)b * 9 * OO * C2;

    // zero halo half2 cells (pos 3 = x col -1, pos 68 = x col 64), both B stages
    for (int i = tid; i < 2 * 16 * 6 * 2; i += 512) {
        int st  = i / 192;
        int rem = i - st * 192;
        int c = rem / 12, r2 = rem - c * 12;
        int rr = r2 >> 1, h = r2 & 1;
        smh[(SB_OFF / 4) + st * (SB_SZ / 4) + c * BCH2 + rr * BROW2 + (h ? 68 : 3)] =
            __halves2half2(__float2half_rn(0.f), __float2half_rn(0.f));
    }

    float acc[4][4][4];
    #pragma unroll
    for (int mi = 0; mi < 4; mi++)
        #pragma unroll
        for (int ni = 0; ni < 4; ni++)
            #pragma unroll
            for (int q = 0; q < 4; q++) acc[mi][ni][q] = 0.f;

    // ---- staging helpers (512 threads)
    auto stageA = [&](int ch) {                      // 1x 16B per thread
        int cg = ch / 9, tap = ch - cg * 9;
        uint32_t dst0 = sbu + (uint32_t)((ch & 3) * SA_SZ);
        const __half2* src0 = wb + ((size_t)tap * OO + o0) * C2 + cg * 16;
        int row = tid >> 2, seg = tid & 3;           // 128 rows x 4 segs of 16 B
        CP16(dst0 + (uint32_t)((row * AST2 + seg * 4) * 4),
             src0 + (size_t)row * C2 + seg * 4);
    };
    auto stageBslice = [&](int cg, int k) {          // one 16B op; k in 0..2
        int j = tid + k * 512;                       // j in [0, 1536)
        int c = j / 96, rem = j - c * 96;            // c = c2-row 0..15
        int row = rem >> 4, seg = rem & 15;          // 6 rows x 16 segs (4 px)
        int rr = r0 - 1 + row;
        bool ok = (unsigned)rr < (unsigned)HH;
        const __half2* src = xb + ((size_t)(cg * 16 + c) * HH + (ok ? rr : 0)) * WW + seg * 4;
        uint32_t dst = sbu + SB_OFF + (uint32_t)((cg & 1) * SB_SZ)
                     + (uint32_t)((c * BCH2 + row * BROW2 + 4 + seg * 4) * 4);
        CP16Z(dst, src, ok ? 16 : 0);
    };

    // boot: group -2 = full B(0) + A(0);  group -1 = A(1)
    #pragma unroll
    for (int k = 0; k < 3; k++) stageBslice(0, k);
    stageA(0);
    CP_COMMIT();
    stageA(1);
    CP_COMMIT();

    for (int ch = 0; ch < 72; ch++) {
        const int cg = ch / 9, tap = ch - cg * 9;

        if (ch + 2 < 72) stageA(ch + 2);
        if (tap >= 1 && tap <= 3 && cg + 1 < 8) stageBslice(cg + 1, tap - 1);
        CP_COMMIT();
        CP_WAIT2();                                   // A(ch) + B(cg) resident
        __syncthreads();

        const int dy = tap / 3 - 1, dx = tap - (tap / 3) * 3 - 1;
        const __half2* A  = smh + (ch & 3) * (SA_SZ / 4) + (wo * 64 + gid) * AST2;
        const __half2* Bc = smh + (SB_OFF / 4) + (cg & 1) * (SB_SZ / 4)
                          + (1 + pr + dy) * BROW2 + 4 + ph * 32 + gid + dx;

        #pragma unroll
        for (int ks = 0; ks < 2; ks++) {
            uint2 alo[4], ahi[4];                     // alo = (a0,a2), ahi = (a1,a3)
            #pragma unroll
            for (int mi = 0; mi < 4; mi++) {
                const __half2* p = A + mi * 16 * AST2 + ks * 8 + kq * 2;
                alo[mi] = *(const uint2*)p;
                ahi[mi] = *(const uint2*)(p + 8 * AST2);
            }
            uint32_t bfr[4][2];
            const __half2* Bk = Bc + (8 * ks + kq) * BCH2;
            #pragma unroll
            for (int ni = 0; ni < 4; ni++) {
                bfr[ni][0] = *(const uint32_t*)(Bk + ni * 8);
                bfr[ni][1] = *(const uint32_t*)(Bk + 4 * BCH2 + ni * 8);
            }
            #pragma unroll
            for (int mi = 0; mi < 4; mi++)
                #pragma unroll
                for (int ni = 0; ni < 4; ni++) {
                    asm volatile(
                        "mma.sync.aligned.m16n8k16.row.col.f32.f16.f16.f32 "
                        "{%0,%1,%2,%3}, {%4,%5,%6,%7}, {%8,%9}, {%0,%1,%2,%3};"
                        : "+f"(acc[mi][ni][0]), "+f"(acc[mi][ni][1]),
                          "+f"(acc[mi][ni][2]), "+f"(acc[mi][ni][3])
                        : "r"(alo[mi].x), "r"(ahi[mi].x), "r"(alo[mi].y), "r"(ahi[mi].y),
                          "r"(bfr[ni][0]), "r"(bfr[ni][1]));
                }
        }
    }

    // epilogue: bias + float2 stores.  px row = r0+pr, col = ph*32 + ni*8 + kq*2
    const float* abp = g_aggb + b * OO;
    #pragma unroll
    for (int mi = 0; mi < 4; mi++) {
        const int o1 = o0 + wo * 64 + mi * 16 + gid;
        const float bv1 = abp[o1], bv2 = abp[o1 + 8];
        float* p1 = out + (((size_t)b * OO + o1) * HH + r0 + pr) * WW + ph * 32 + 2 * kq;
        float* p2 = p1 + (size_t)8 * HH * WW;
        #pragma unroll
        for (int ni = 0; ni < 4; ni++) {
            *(float2*)(p1 + ni * 8) = make_float2(acc[mi][ni][0] + bv1, acc[mi][ni][1] + bv1);
            *(float2*)(p2 + ni * 8) = make_float2(acc[mi][ni][2] + bv2, acc[mi][ni][3] + bv2);
        }
    }
}

// ---------------------------------------------------------------------------
extern "C" void kernel_launch(void* const* d_in, const int* in_sizes, int n_in,
                              void* d_out, int out_size) {
    const float* x      = (const float*)d_in[0];
    const float* w_fc1  = (const float*)d_in[1];
    const float* w_fc2  = (const float*)d_in[2];
    const float* b_fc2  = (const float*)d_in[3];
    const float* weight = (const float*)d_in[4];
    const float* bias   = (const float*)d_in[5];
    float* out = (float*)d_out;

    cudaFuncSetAttribute(conv_mma_kernel,
                         cudaFuncAttributeMaxDynamicSharedMemorySize, SMEM_TOTAL);

    pool_kernel<<<BB * C2, 256>>>(x);
    att_kernel<<<BB, 128>>>(w_fc1, w_fc2, b_fc2, bias);
    aggw_kernel<<<OO, 128>>>(weight);
    conv_mma_kernel<<<dim3(BB, OO / 128, HH / 4), 512, SMEM_TOTAL>>>(out);
}